// round 7
// baseline (speedup 1.0000x reference)
#include <cuda_runtime.h>
#include <cstdint>

// Problem constants
#define B_   32
#define L_   4096
#define C_   512
#define NP_  32
#define DM_  512
#define M_   (B_*C_*NP_)                       // 524288 GEMM rows

#define SEASON_ELEMS ((size_t)M_*DM_)          // 268435456
#define TREND_ELEMS  ((size_t)B_*C_*L_)        // 67108864

// season scratch in [b,c,l] layout == [M][128] row-major
__device__ float g_season[TREND_ELEMS];        // 256 MB static scratch

// ===================== EMA scan =============================================
// trend[0]=x[0]; trend[i]=(1-a)*trend[i-1]+a*x[i] per (b,c).
// (0.7)^128 ~ 1.6e-20 << fp32 eps -> 128-step warmup makes 512-chunks independent.
#define CHUNK 512
#define WARM  128
#define TL    32          // l-steps buffered per warp before coalesced store

__global__ __launch_bounds__(128)
void ema_kernel(const float* __restrict__ x,
                const float* __restrict__ alpha,
                float* __restrict__ trend_out,
                int write_trend)
{
    __shared__ float bufS[4][TL*33];    // per-warp transpose buffers (33 pitch:
    __shared__ float bufT[4][TL*33];    //  conflict-free both phases)
    const int warp = threadIdx.x >> 5;
    const int lane = threadIdx.x & 31;
    const int cbase = blockIdx.y * 128 + warp * 32;
    const int c     = cbase + lane;
    const int b     = blockIdx.z;
    const int l0    = blockIdx.x * CHUNK;

    const float a  = alpha[c];
    const float am = 1.0f - a;
    const float* xb = x + (size_t)b * L_ * C_ + c;    // stride C_ along l

    float t = 0.0f;
    if (blockIdx.x) {   // warmup to make chunk independent
        const float* xw = xb + (size_t)(l0 - WARM) * C_;
        t = xw[0];
        #pragma unroll 8
        for (int i = 1; i < WARM; ++i)
            t = fmaf(am, t, a * xw[(size_t)i * C_]);
    }

    float* sS = bufS[warp];
    float* sT = bufT[warp];
    const size_t rowbase = (size_t)b * C_ + cbase;

    for (int tile = 0; tile < CHUNK / TL; ++tile) {
        const int lt = l0 + tile * TL;
        const float* xp = xb + (size_t)lt * C_;
        float xv[TL];
        #pragma unroll
        for (int i = 0; i < TL; ++i)
            xv[i] = xp[(size_t)i * C_];               // 128B coalesced across c
        #pragma unroll
        for (int i = 0; i < TL; ++i) {
            if (blockIdx.x == 0 && tile == 0 && i == 0) t = xv[0];
            else                                        t = fmaf(am, t, a * xv[i]);
            sT[lane * 33 + i] = t;                    // bank (lane+i)%32: clean
            sS[lane * 33 + i] = xv[i] - t;
        }
        __syncwarp();
        // transposed store: one full 128B line per instruction per warp
        #pragma unroll
        for (int cc = 0; cc < TL; ++cc)
            g_season[(rowbase + cc) * L_ + lt + lane] = sS[cc * 33 + lane];
        if (write_trend) {
            #pragma unroll
            for (int cc = 0; cc < TL; ++cc)
                trend_out[(rowbase + cc) * L_ + lt + lane] = sT[cc * 33 + lane];
        }
        __syncwarp();
    }
}

// ===================== tf32 GEMM: out[M,512] = season[M,128] @ W[128,512] ====
// One CTA owns 128 rows x ALL 512 cols -> A read exactly once (kills the 4x
// A re-read). B (W slice, L2-resident) double-buffered via cp.async so the
// tensor pipe never waits on loads.
#define BM  128
#define KK  128
#define BNC 128                 // N per chunk (4 chunks)
#define AP  132                 // A pitch (mod32==4 -> conflict-free frags)
#define BP  136                 // B pitch (mod32==8 -> conflict-free frags)
#define SA  (BM*AP)
#define SB  (KK*BP)
#define SMEM_BYTES ((SA + 2*SB) * 4)   // 206848 B

__device__ __forceinline__ uint32_t f2tf(float f) {
    uint32_t u;
    asm("cvt.rna.tf32.f32 %0, %1;" : "=r"(u) : "f"(f));
    return u;
}
__device__ __forceinline__ void cpa16(float* dst, const float* src) {
    uint32_t s = (uint32_t)__cvta_generic_to_shared(dst);
    asm volatile("cp.async.cg.shared.global [%0], [%1], 16;\n" :: "r"(s), "l"(src));
}

__global__ __launch_bounds__(256)
void gemm_kernel(const float* __restrict__ W, float* __restrict__ out)
{
    extern __shared__ float smem[];
    float* As = smem;                          // [BM][AP] raw f32
    const int tid = threadIdx.x;
    const size_t m0 = (size_t)blockIdx.x * BM;
    const float* A = g_season + m0 * KK;       // K contiguous

    // A tile: once per CTA
    #pragma unroll
    for (int it = 0; it < 16; ++it) {
        const int i = tid + it * 256, r = i >> 5, c4 = (i & 31) << 2;
        cpa16(As + r * AP + c4, A + (size_t)r * KK + c4);
    }
    // B chunk 0
    {
        float* B0 = smem + SA;
        #pragma unroll
        for (int it = 0; it < 16; ++it) {
            const int i = tid + it * 256, r = i >> 5, c4 = (i & 31) << 2;
            cpa16(B0 + r * BP + c4, W + (size_t)r * DM_ + c4);
        }
    }
    asm volatile("cp.async.commit_group;\n");
    asm volatile("cp.async.wait_group 0;\n");
    __syncthreads();

    const int warp = tid >> 5, lane = tid & 31;
    const int wm = (warp & 1) * 64;            // 2x4 warp grid, 64x32 warp tile
    const int wn = (warp >> 1) * 32;
    const int g  = lane >> 2;
    const int tg = lane & 3;

    for (int j = 0; j < 4; ++j) {
        if (j < 3) {   // prefetch next B chunk into the other buffer
            float* Bn = smem + SA + (size_t)((j + 1) & 1) * SB;
            #pragma unroll
            for (int it = 0; it < 16; ++it) {
                const int i = tid + it * 256, r = i >> 5, c4 = (i & 31) << 2;
                cpa16(Bn + r * BP + c4, W + (size_t)r * DM_ + (j + 1) * BNC + c4);
            }
            asm volatile("cp.async.commit_group;\n");
        }
        const float* Bc = smem + SA + (size_t)(j & 1) * SB;

        float acc[4][4][4];
        #pragma unroll
        for (int a0 = 0; a0 < 4; ++a0)
            #pragma unroll
            for (int a1 = 0; a1 < 4; ++a1)
                #pragma unroll
                for (int a2 = 0; a2 < 4; ++a2) acc[a0][a1][a2] = 0.0f;

        #pragma unroll
        for (int ks = 0; ks < KK; ks += 8) {
            uint32_t af[4][4], bf[4][2];
            #pragma unroll
            for (int mf = 0; mf < 4; ++mf) {
                const float* ap = As + (wm + mf * 16 + g) * AP + ks + tg;
                af[mf][0] = f2tf(ap[0]);
                af[mf][1] = f2tf(ap[8 * AP]);
                af[mf][2] = f2tf(ap[4]);
                af[mf][3] = f2tf(ap[8 * AP + 4]);
            }
            #pragma unroll
            for (int nf = 0; nf < 4; ++nf) {
                const float* bp = Bc + (ks + tg) * BP + wn + nf * 8 + g;
                bf[nf][0] = f2tf(bp[0]);
                bf[nf][1] = f2tf(bp[4 * BP]);
            }
            #pragma unroll
            for (int mf = 0; mf < 4; ++mf)
                #pragma unroll
                for (int nf = 0; nf < 4; ++nf)
                    asm volatile(
                        "mma.sync.aligned.m16n8k8.row.col.f32.tf32.tf32.f32 "
                        "{%0,%1,%2,%3}, {%4,%5,%6,%7}, {%8,%9}, {%0,%1,%2,%3};\n"
                        : "+f"(acc[mf][nf][0]), "+f"(acc[mf][nf][1]),
                          "+f"(acc[mf][nf][2]), "+f"(acc[mf][nf][3])
                        : "r"(af[mf][0]), "r"(af[mf][1]), "r"(af[mf][2]), "r"(af[mf][3]),
                          "r"(bf[nf][0]), "r"(bf[nf][1]));
        }

        // epilogue for this 128-col slab (sector-aligned float2 stores)
        const int n0 = j * BNC;
        #pragma unroll
        for (int mf = 0; mf < 4; ++mf) {
            const size_t r0 = m0 + wm + mf * 16 + g;
            #pragma unroll
            for (int nf = 0; nf < 4; ++nf) {
                const int col = n0 + wn + nf * 8 + tg * 2;
                *reinterpret_cast<float2*>(out + r0 * DM_ + col) =
                    make_float2(acc[mf][nf][0], acc[mf][nf][1]);
                *reinterpret_cast<float2*>(out + (r0 + 8) * DM_ + col) =
                    make_float2(acc[mf][nf][2], acc[mf][nf][3]);
            }
        }

        if (j < 3) {
            asm volatile("cp.async.wait_group 0;\n");
            __syncthreads();
        }
    }
}

// ===================== launch ===============================================
extern "C" void kernel_launch(void* const* d_in, const int* in_sizes, int n_in,
                              void* d_out, int out_size)
{
    const float* x     = (const float*)d_in[0];   // [B,L,C]
    // d_in[1] = x_mark (unused)
    const float* alpha = (const float*)d_in[2];   // [1,C]
    const float* W     = (const float*)d_in[3];   // [P,DM]

    float* out_season = (float*)d_out;
    const int write_trend = ((size_t)out_size >= SEASON_ELEMS + TREND_ELEMS) ? 1 : 0;
    float* out_trend = write_trend ? out_season + SEASON_ELEMS : out_season;

    ema_kernel<<<dim3(L_/CHUNK, C_/128, B_), 128>>>(x, alpha, out_trend, write_trend);

    cudaFuncSetAttribute(gemm_kernel,
                         cudaFuncAttributeMaxDynamicSharedMemorySize, SMEM_BYTES);
    gemm_kernel<<<M_/BM, 256, SMEM_BYTES>>>(W, out_season);
}

// round 9
// speedup vs baseline: 1.0519x; 1.0519x over previous
#include <cuda_runtime.h>
#include <cstdint>

// Problem constants
#define B_   32
#define L_   4096
#define C_   512
#define NP_  32
#define DM_  512
#define M_   (B_*C_*NP_)                       // 524288 GEMM rows
#define KK   128

#define SEASON_ELEMS ((size_t)M_*DM_)          // 268435456
#define TREND_ELEMS  ((size_t)B_*C_*L_)        // 67108864

// season scratch in [b,c,l] layout == [M][128] row-major, tf32-pre-rounded
__device__ float g_season[TREND_ELEMS];        // 256 MB static scratch
__device__ float g_wr[KK*DM_];                 // W [k][n], tf32-pre-rounded

__device__ __forceinline__ float tf32r(float f) {
    uint32_t u; asm("cvt.rna.tf32.f32 %0, %1;" : "=r"(u) : "f"(f));
    return __uint_as_float(u);
}
__device__ __forceinline__ void cpa16(float* dst, const float* src) {
    uint32_t s = (uint32_t)__cvta_generic_to_shared(dst);
    asm volatile("cp.async.cg.shared.global [%0], [%1], 16;\n" :: "r"(s), "l"(src));
}

// ===================== EMA scan =============================================
// trend[0]=x[0]; trend[i]=(1-a)*trend[i-1]+a*x[i] per (b,c).
// (0.7)^128 ~ 1.6e-20 << fp32 eps -> 128-step warmup makes 512-chunks independent.
#define CHUNK 512
#define WARM  128
#define TL    32

__global__ __launch_bounds__(128)
void ema_kernel(const float* __restrict__ x,
                const float* __restrict__ alpha,
                float* __restrict__ trend_out,
                int write_trend)
{
    __shared__ float bufS[4][TL*33];
    __shared__ float bufT[4][TL*33];
    const int warp = threadIdx.x >> 5;
    const int lane = threadIdx.x & 31;
    const int cbase = blockIdx.y * 128 + warp * 32;
    const int c     = cbase + lane;
    const int b     = blockIdx.z;
    const int l0    = blockIdx.x * CHUNK;

    const float a  = alpha[c];
    const float am = 1.0f - a;
    const float* xb = x + (size_t)b * L_ * C_ + c;

    float t = 0.0f;
    if (blockIdx.x) {
        const float* xw = xb + (size_t)(l0 - WARM) * C_;
        t = xw[0];
        #pragma unroll 8
        for (int i = 1; i < WARM; ++i)
            t = fmaf(am, t, a * xw[(size_t)i * C_]);
    }

    float* sS = bufS[warp];
    float* sT = bufT[warp];
    const size_t rowbase = (size_t)b * C_ + cbase;

    for (int tile = 0; tile < CHUNK / TL; ++tile) {
        const int lt = l0 + tile * TL;
        const float* xp = xb + (size_t)lt * C_;
        float xv[TL];
        #pragma unroll
        for (int i = 0; i < TL; ++i)
            xv[i] = xp[(size_t)i * C_];               // 128B coalesced across c
        #pragma unroll
        for (int i = 0; i < TL; ++i) {
            if (blockIdx.x == 0 && tile == 0 && i == 0) t = xv[0];
            else                                        t = fmaf(am, t, a * xv[i]);
            sT[lane * 33 + i] = t;
            sS[lane * 33 + i] = tf32r(xv[i] - t);     // pre-round for MMA
        }
        __syncwarp();
        #pragma unroll
        for (int cc = 0; cc < TL; ++cc)
            g_season[(rowbase + cc) * L_ + lt + lane] = sS[cc * 33 + lane];
        if (write_trend) {
            #pragma unroll
            for (int cc = 0; cc < TL; ++cc)
                trend_out[(rowbase + cc) * L_ + lt + lane] = sT[cc * 33 + lane];
        }
        __syncwarp();
    }
}

// ===================== W prep: tf32-round in place layout [k][n] ============
__global__ void wprep_kernel(const float* __restrict__ W)
{
    int i = blockIdx.x * 256 + threadIdx.x;    // 0..65535
    g_wr[i] = tf32r(W[i]);
}

// ===================== tf32 GEMM: out[M,512] = season[M,128] @ W[128,512] ===
// CTA = 128 rows x all 512 cols (A read exactly once). B double-buffered via
// cp.async. A stored in PERMUTED smem layout so each thread's fragment pair
// (k=tg, k=tg+4) is one LDS.64: within each 8-float k-group the store order is
// [c0,c4,c1,c5,c2,c6,c3,c7]  (position p(c) = (c&3)*2 + ((c>>2)&1)).
#define BM  128
#define BNC 128                 // N per chunk (4 chunks)
#define AP  136                 // A pitch: mod32==8 -> LDS.64 conflict-free
#define BP  136                 // B pitch: mod32==8 -> LDS.32 (8tg+g) conflict-free
#define SA  (BM*AP)
#define SB  (KK*BP)
#define SMEM_BYTES ((SA + 2*SB) * 4)   // 208896 B

__global__ __launch_bounds__(256)
void gemm_kernel(float* __restrict__ out)
{
    extern __shared__ float smem[];
    float* As = smem;                          // [BM][AP] permuted tf32
    const int tid = threadIdx.x;
    const size_t m0 = (size_t)blockIdx.x * BM;
    const float* A = g_season + m0 * KK;

    // ---- B chunk 0 via cp.async (plain [k][n] layout) ----
    {
        float* B0 = smem + SA;
        #pragma unroll
        for (int it = 0; it < 16; ++it) {
            const int i = tid + it * 256, r = i >> 5, c4 = (i & 31) << 2;
            cpa16(B0 + r * BP + c4, g_wr + (size_t)r * DM_ + c4);
        }
        asm volatile("cp.async.commit_group;\n");
    }
    // ---- A tile once, with k-group permutation (LDG.128x2 -> STS.128x2) ----
    #pragma unroll
    for (int it = 0; it < 8; ++it) {
        const int gi = tid + it * 256;         // 0..2047 8-float groups
        const int r = gi >> 4, grp = gi & 15;
        const float4* src = reinterpret_cast<const float4*>(A + (size_t)r * KK + grp * 8);
        const float4 v0 = src[0], v1 = src[1];
        float* dst = As + r * AP + grp * 8;
        reinterpret_cast<float4*>(dst)[0] = make_float4(v0.x, v1.x, v0.y, v1.y);
        reinterpret_cast<float4*>(dst)[1] = make_float4(v0.z, v1.z, v0.w, v1.w);
    }
    asm volatile("cp.async.wait_group 0;\n" ::: "memory");
    __syncthreads();

    const int warp = tid >> 5, lane = tid & 31;
    const int wm = (warp & 1) * 64;            // 2x4 warp grid, 64x32 warp tile
    const int wn = (warp >> 1) * 32;
    const int g  = lane >> 2;
    const int tg = lane & 3;

    for (int j = 0; j < 4; ++j) {
        if (j < 3) {   // prefetch next B chunk into the other buffer
            float* Bn = smem + SA + (size_t)((j + 1) & 1) * SB;
            #pragma unroll
            for (int it = 0; it < 16; ++it) {
                const int i = tid + it * 256, r = i >> 5, c4 = (i & 31) << 2;
                cpa16(Bn + r * BP + c4, g_wr + (size_t)r * DM_ + (j + 1) * BNC + c4);
            }
            asm volatile("cp.async.commit_group;\n");
        }
        const float* Bc = smem + SA + (size_t)(j & 1) * SB;

        float acc[4][4][4];
        #pragma unroll
        for (int a0 = 0; a0 < 4; ++a0)
            #pragma unroll
            for (int a1 = 0; a1 < 4; ++a1)
                #pragma unroll
                for (int a2 = 0; a2 < 4; ++a2) acc[a0][a1][a2] = 0.0f;

        #pragma unroll
        for (int ks = 0; ks < KK; ks += 8) {
            uint32_t af[4][4], bf[4][2];
            #pragma unroll
            for (int mf = 0; mf < 4; ++mf) {
                // permuted layout: one LDS.64 = (k=ks+tg, k=ks+tg+4)
                const float2 lo = *reinterpret_cast<const float2*>(
                    As + (wm + mf * 16 + g) * AP + ks + 2 * tg);
                const float2 hi = *reinterpret_cast<const float2*>(
                    As + (wm + mf * 16 + g + 8) * AP + ks + 2 * tg);
                af[mf][0] = __float_as_uint(lo.x);   // (g,   tg)
                af[mf][1] = __float_as_uint(hi.x);   // (g+8, tg)
                af[mf][2] = __float_as_uint(lo.y);   // (g,   tg+4)
                af[mf][3] = __float_as_uint(hi.y);   // (g+8, tg+4)
            }
            #pragma unroll
            for (int nf = 0; nf < 4; ++nf) {
                const float* bp = Bc + (ks + tg) * BP + wn + nf * 8 + g;
                bf[nf][0] = __float_as_uint(bp[0]);        // (k=tg,   n=g)
                bf[nf][1] = __float_as_uint(bp[4 * BP]);   // (k=tg+4, n=g)
            }
            #pragma unroll
            for (int mf = 0; mf < 4; ++mf)
                #pragma unroll
                for (int nf = 0; nf < 4; ++nf)
                    asm volatile(
                        "mma.sync.aligned.m16n8k8.row.col.f32.tf32.tf32.f32 "
                        "{%0,%1,%2,%3}, {%4,%5,%6,%7}, {%8,%9}, {%0,%1,%2,%3};\n"
                        : "+f"(acc[mf][nf][0]), "+f"(acc[mf][nf][1]),
                          "+f"(acc[mf][nf][2]), "+f"(acc[mf][nf][3])
                        : "r"(af[mf][0]), "r"(af[mf][1]), "r"(af[mf][2]), "r"(af[mf][3]),
                          "r"(bf[nf][0]), "r"(bf[nf][1]));
        }

        // ---- epilogue for this 128-col slab (sector-aligned float2 stores) ----
        const int n0 = j * BNC;
        #pragma unroll
        for (int mf = 0; mf < 4; ++mf) {
            const size_t r0 = m0 + wm + mf * 16 + g;
            #pragma unroll
            for (int nf = 0; nf < 4; ++nf) {
                const int col = n0 + wn + nf * 8 + tg * 2;
                *reinterpret_cast<float2*>(out + r0 * DM_ + col) =
                    make_float2(acc[mf][nf][0], acc[mf][nf][1]);
                *reinterpret_cast<float2*>(out + (r0 + 8) * DM_ + col) =
                    make_float2(acc[mf][nf][2], acc[mf][nf][3]);
            }
        }

        if (j < 3) {
            asm volatile("cp.async.wait_group 0;\n" ::: "memory");
            __syncthreads();
        }
    }
}

// ===================== launch ===============================================
extern "C" void kernel_launch(void* const* d_in, const int* in_sizes, int n_in,
                              void* d_out, int out_size)
{
    const float* x     = (const float*)d_in[0];   // [B,L,C]
    // d_in[1] = x_mark (unused)
    const float* alpha = (const float*)d_in[2];   // [1,C]
    const float* W     = (const float*)d_in[3];   // [P,DM]

    float* out_season = (float*)d_out;
    const int write_trend = ((size_t)out_size >= SEASON_ELEMS + TREND_ELEMS) ? 1 : 0;
    float* out_trend = write_trend ? out_season + SEASON_ELEMS : out_season;

    wprep_kernel<<<KK*DM_/256, 256>>>(W);
    ema_kernel<<<dim3(L_/CHUNK, C_/128, B_), 128>>>(x, alpha, out_trend, write_trend);

    cudaFuncSetAttribute(gemm_kernel,
                         cudaFuncAttributeMaxDynamicSharedMemorySize, SMEM_BYTES);
    gemm_kernel<<<M_/BM, 256, SMEM_BYTES>>>(out_season);
}